// round 2
// baseline (speedup 1.0000x reference)
#include <cuda_runtime.h>
#include <math.h>

#define BB 8
#define NN 1024
#define DIM 768
#define NH 12
#define HD 64
#define SCALE 0.125f   // HD^-0.5 = 1/8

// Scratch (allocation-free rule: __device__ globals)
__device__ float g_kv[(size_t)BB * NN * 2 * DIM];   // [B, N, 2*DIM]  ~50 MB
__device__ float g_wa[(size_t)BB * NN * DIM];       // [B, N, DIM]    ~25 MB

// ---------------------------------------------------------------------------
// Tiled SGEMM with bias:  C[M,Nc] = A[M,K] @ W[K,Nc] + bias[Nc]
// BM=BN=64, BK=16, 256 threads, 4x4 per thread.
// Requires M%64==0, Nc%64==0, K%16==0 (all hold here).
// ---------------------------------------------------------------------------
__global__ void gemm_bias_kernel(const float* __restrict__ A,
                                 const float* __restrict__ W,
                                 const float* __restrict__ bias,
                                 float* __restrict__ C,
                                 int M, int Nc, int K)
{
    __shared__ float As[64 * 16];
    __shared__ float Bs[16 * 64];

    const int tid = threadIdx.x;           // 0..255
    const int tx = tid & 15;               // 0..15 -> C cols
    const int ty = tid >> 4;               // 0..15 -> C rows
    const int row0 = blockIdx.y * 64;
    const int col0 = blockIdx.x * 64;

    float acc[4][4] = {};

    // A-tile load mapping: one float4 per thread
    const int ar = tid >> 2;               // 0..63
    const int ac4 = (tid & 3) << 2;        // 0,4,8,12
    // W-tile load mapping
    const int br = tid >> 4;               // 0..15
    const int bc4 = (tid & 15) << 2;       // 0..60

    for (int k0 = 0; k0 < K; k0 += 16) {
        float4 av = *(const float4*)(A + (size_t)(row0 + ar) * K + k0 + ac4);
        *(float4*)&As[ar * 16 + ac4] = av;
        float4 bv = *(const float4*)(W + (size_t)(k0 + br) * Nc + col0 + bc4);
        *(float4*)&Bs[br * 64 + bc4] = bv;
        __syncthreads();

        #pragma unroll
        for (int kk = 0; kk < 16; kk++) {
            float a[4];
            #pragma unroll
            for (int i = 0; i < 4; i++) a[i] = As[(ty * 4 + i) * 16 + kk];
            float4 b4 = *(float4*)&Bs[kk * 64 + tx * 4];
            #pragma unroll
            for (int i = 0; i < 4; i++) {
                acc[i][0] += a[i] * b4.x;
                acc[i][1] += a[i] * b4.y;
                acc[i][2] += a[i] * b4.z;
                acc[i][3] += a[i] * b4.w;
            }
        }
        __syncthreads();
    }

    float4 bb = *(const float4*)&bias[col0 + tx * 4];
    #pragma unroll
    for (int i = 0; i < 4; i++) {
        int row = row0 + ty * 4 + i;
        float4 out;
        out.x = acc[i][0] + bb.x;
        out.y = acc[i][1] + bb.y;
        out.z = acc[i][2] + bb.z;
        out.w = acc[i][3] + bb.w;
        *(float4*)&C[(size_t)row * Nc + col0 + tx * 4] = out;
    }
}

// ---------------------------------------------------------------------------
// Flash-attention (one pass, online softmax).
// Grid: (B*H, N/64). Block: 256 threads (16x16 logical).
// Each block: 64 queries x full 1024 keys, HD=64.
// Q from dec, K/V from g_kv, output to g_wa.
// Dynamic smem: Qs[64*64] Ks[64*65] Vs[64*64] Ps[64*64]  (~65.8 KB)
// ---------------------------------------------------------------------------
__global__ void attn_kernel(const float* __restrict__ dec)
{
    extern __shared__ float sm[];
    float* Qs = sm;                 // 64*64
    float* Ks = Qs + 64 * 64;       // 64*65 (padded rows)
    float* Vs = Ks + 64 * 65;       // 64*64
    float* Ps = Vs + 64 * 64;       // 64*64

    const int bh = blockIdx.x;
    const int b = bh / NH;
    const int h = bh % NH;
    const int q0 = blockIdx.y * 64;

    const int tid = threadIdx.x;
    const int tx = tid & 15;        // key-col group / out-dim group
    const int ty = tid >> 4;        // query-row group

    // Load Q tile [64 x 64] (row-major, float4)
    // 64 rows * 16 float4 per row = 1024 float4, 256 threads -> 4 iters
    for (int it = 0; it < 4; it++) {
        int t = tid + it * 256;        // 0..1023
        int rr = t >> 4;               // 0..63
        int cc = (t & 15) << 2;        // 0..60
        float4 v = *(const float4*)(dec + (size_t)(b * NN + q0 + rr) * DIM
                                    + h * HD + cc);
        *(float4*)&Qs[rr * 64 + cc] = v;
    }

    float m[4], l[4], o[4][4];
    #pragma unroll
    for (int i = 0; i < 4; i++) {
        m[i] = -1e30f; l[i] = 0.f;
        #pragma unroll
        for (int j = 0; j < 4; j++) o[i][j] = 0.f;
    }

    const float* kbase = g_kv + (size_t)b * NN * 2 * DIM + h * HD;
    const float* vbase = kbase + DIM;

    for (int k0 = 0; k0 < NN; k0 += 64) {
        __syncthreads();   // protect Ks/Vs from previous iteration readers

        // Load K tile (padded rows of 65) and V tile (rows of 64)
        for (int it = 0; it < 4; it++) {
            int t = tid + it * 256;
            int rr = t >> 4;
            int cc = (t & 15) << 2;
            float4 kv4 = *(const float4*)(kbase + (size_t)(k0 + rr) * (2 * DIM) + cc);
            Ks[rr * 65 + cc + 0] = kv4.x;
            Ks[rr * 65 + cc + 1] = kv4.y;
            Ks[rr * 65 + cc + 2] = kv4.z;
            Ks[rr * 65 + cc + 3] = kv4.w;
            float4 vv4 = *(const float4*)(vbase + (size_t)(k0 + rr) * (2 * DIM) + cc);
            *(float4*)&Vs[rr * 64 + cc] = vv4;
        }
        __syncthreads();

        // S = Q @ K^T for this 64x64 tile (each thread 4x4)
        float s[4][4] = {};
        #pragma unroll 8
        for (int d = 0; d < 64; d++) {
            float a[4], kk[4];
            #pragma unroll
            for (int i = 0; i < 4; i++) a[i] = Qs[(ty * 4 + i) * 64 + d];
            #pragma unroll
            for (int j = 0; j < 4; j++) kk[j] = Ks[(tx * 4 + j) * 65 + d];
            #pragma unroll
            for (int i = 0; i < 4; i++)
                #pragma unroll
                for (int j = 0; j < 4; j++)
                    s[i][j] += a[i] * kk[j];
        }

        // Online softmax per query row (16 lanes of width-16 shuffle groups
        // correspond exactly to the tx-groups sharing a query row)
        #pragma unroll
        for (int i = 0; i < 4; i++) {
            float mt = -1e30f;
            #pragma unroll
            for (int j = 0; j < 4; j++) {
                s[i][j] *= SCALE;
                mt = fmaxf(mt, s[i][j]);
            }
            #pragma unroll
            for (int off = 8; off > 0; off >>= 1)
                mt = fmaxf(mt, __shfl_xor_sync(0xffffffffu, mt, off, 16));

            float mn = fmaxf(m[i], mt);
            float corr = __expf(m[i] - mn);
            m[i] = mn;
            l[i] *= corr;
            #pragma unroll
            for (int j = 0; j < 4; j++) o[i][j] *= corr;

            float p0 = __expf(s[i][0] - mn);
            float p1 = __expf(s[i][1] - mn);
            float p2 = __expf(s[i][2] - mn);
            float p3 = __expf(s[i][3] - mn);
            float rs = p0 + p1 + p2 + p3;
            float4 pv; pv.x = p0; pv.y = p1; pv.z = p2; pv.w = p3;
            #pragma unroll
            for (int off = 8; off > 0; off >>= 1)
                rs += __shfl_xor_sync(0xffffffffu, rs, off, 16);
            l[i] += rs;

            *(float4*)&Ps[(ty * 4 + i) * 64 + tx * 4] = pv;
        }
        __syncthreads();

        // O += P @ V   (each thread: 4 query rows x 4 out dims)
        #pragma unroll 8
        for (int j = 0; j < 64; j++) {
            float p[4];
            #pragma unroll
            for (int i = 0; i < 4; i++) p[i] = Ps[(ty * 4 + i) * 64 + j];
            float4 v4 = *(float4*)&Vs[j * 64 + tx * 4];
            #pragma unroll
            for (int i = 0; i < 4; i++) {
                o[i][0] += p[i] * v4.x;
                o[i][1] += p[i] * v4.y;
                o[i][2] += p[i] * v4.z;
                o[i][3] += p[i] * v4.w;
            }
        }
    }

    // Epilogue: normalize and store to g_wa [B, N, DIM]
    #pragma unroll
    for (int i = 0; i < 4; i++) {
        float inv = 1.f / l[i];
        int row = q0 + ty * 4 + i;
        float4 out;
        out.x = o[i][0] * inv;
        out.y = o[i][1] * inv;
        out.z = o[i][2] * inv;
        out.w = o[i][3] * inv;
        *(float4*)&g_wa[(size_t)(b * NN + row) * DIM + h * HD + tx * 4] = out;
    }
}

// ---------------------------------------------------------------------------
// Launcher
// ---------------------------------------------------------------------------
extern "C" void kernel_launch(void* const* d_in, const int* in_sizes, int n_in,
                              void* d_out, int out_size)
{
    const float* en    = (const float*)d_in[0];
    const float* dec   = (const float*)d_in[1];
    const float* Wkv   = (const float*)d_in[2];
    const float* bkv   = (const float*)d_in[3];
    const float* Wproj = (const float*)d_in[4];
    const float* bproj = (const float*)d_in[5];
    float* out = (float*)d_out;

    float* kv = nullptr;
    float* wa = nullptr;
    cudaGetSymbolAddress((void**)&kv, g_kv);
    cudaGetSymbolAddress((void**)&wa, g_wa);

    const int M = BB * NN;       // 8192

    // 1) kv = en @ Wkv + bkv    [8192 x 1536] = [8192 x 768] @ [768 x 1536]
    {
        dim3 grid((2 * DIM) / 64, M / 64);
        gemm_bias_kernel<<<grid, 256>>>(en, Wkv, bkv, kv, M, 2 * DIM, DIM);
    }

    // 2) flash attention -> wa  [8192 x 768]
    {
        const int smem = (64 * 64 + 64 * 65 + 64 * 64 + 64 * 64) * (int)sizeof(float);
        (void)cudaFuncSetAttribute(attn_kernel,
                                   cudaFuncAttributeMaxDynamicSharedMemorySize, smem);
        dim3 grid(BB * NH, NN / 64);
        attn_kernel<<<grid, 256, smem>>>(dec);
    }

    // 3) out = wa @ Wproj + bproj   [8192 x 768] = [8192 x 768] @ [768 x 768]
    {
        dim3 grid(DIM / 64, M / 64);
        gemm_bias_kernel<<<grid, 256>>>(wa, Wproj, bproj, out, M, DIM, DIM);
    }
}

// round 4
// speedup vs baseline: 1.0206x; 1.0206x over previous
#include <cuda_runtime.h>
#include <math.h>

#define BB 8
#define NN 1024
#define DIM 768
#define NH 12
#define HD 64
#define SCALE 0.125f   // HD^-0.5

// Scratch (allocation-free rule: __device__ globals)
__device__ float g_kv[(size_t)BB * NN * 2 * DIM];   // [B, N, 2*DIM]
__device__ float g_wa[(size_t)BB * NN * DIM];       // [B, N, DIM]

// ---------------------------------------------------------------------------
// SGEMM + bias: C[M,Nc] = A[M,K] @ W[K,Nc] + bias
// 128x128 tile, BK=8, 256 threads, 8x8 per thread. 1 B of LDS per FMA.
// ---------------------------------------------------------------------------
__global__ __launch_bounds__(256, 2)
void gemm_bias_kernel(const float* __restrict__ A,
                      const float* __restrict__ W,
                      const float* __restrict__ bias,
                      float* __restrict__ C,
                      int M, int Nc, int K)
{
    __shared__ float As[8][128];   // transposed: As[k][row]
    __shared__ float Bs[8][128];

    const int tid = threadIdx.x;       // 0..255
    const int tx = tid & 15;           // col group (8 cols)
    const int ty = tid >> 4;           // row group (8 rows)
    const int row0 = blockIdx.y * 128;
    const int col0 = blockIdx.x * 128;

    // Global->smem mappings (one float4 each)
    const int ar = tid >> 1;           // 0..127 (A row)
    const int ac = (tid & 1) * 4;      // 0 or 4 (A col in k-slab)
    const int br = tid >> 5;           // 0..7   (W row in k-slab)
    const int bc = (tid & 31) * 4;     // 0..124 (W col)

    float acc[8][8];
    #pragma unroll
    for (int i = 0; i < 8; i++)
        #pragma unroll
        for (int j = 0; j < 8; j++) acc[i][j] = 0.f;

    for (int k0 = 0; k0 < K; k0 += 8) {
        float4 av = *(const float4*)(A + (size_t)(row0 + ar) * K + k0 + ac);
        float4 bv = *(const float4*)(W + (size_t)(k0 + br) * Nc + col0 + bc);
        __syncthreads();
        As[ac + 0][ar] = av.x;
        As[ac + 1][ar] = av.y;
        As[ac + 2][ar] = av.z;
        As[ac + 3][ar] = av.w;
        *(float4*)&Bs[br][bc] = bv;
        __syncthreads();

        #pragma unroll
        for (int kk = 0; kk < 8; kk++) {
            float4 a0 = *(float4*)&As[kk][ty * 8];
            float4 a1 = *(float4*)&As[kk][ty * 8 + 4];
            float4 b0 = *(float4*)&Bs[kk][tx * 8];
            float4 b1 = *(float4*)&Bs[kk][tx * 8 + 4];
            float a[8] = {a0.x, a0.y, a0.z, a0.w, a1.x, a1.y, a1.z, a1.w};
            float b[8] = {b0.x, b0.y, b0.z, b0.w, b1.x, b1.y, b1.z, b1.w};
            #pragma unroll
            for (int i = 0; i < 8; i++)
                #pragma unroll
                for (int j = 0; j < 8; j++)
                    acc[i][j] += a[i] * b[j];
        }
    }

    float4 bb0 = *(const float4*)&bias[col0 + tx * 8];
    float4 bb1 = *(const float4*)&bias[col0 + tx * 8 + 4];
    float bbv[8] = {bb0.x, bb0.y, bb0.z, bb0.w, bb1.x, bb1.y, bb1.z, bb1.w};
    #pragma unroll
    for (int i = 0; i < 8; i++) {
        int row = row0 + ty * 8 + i;
        float4 o0, o1;
        o0.x = acc[i][0] + bbv[0]; o0.y = acc[i][1] + bbv[1];
        o0.z = acc[i][2] + bbv[2]; o0.w = acc[i][3] + bbv[3];
        o1.x = acc[i][4] + bbv[4]; o1.y = acc[i][5] + bbv[5];
        o1.z = acc[i][6] + bbv[6]; o1.w = acc[i][7] + bbv[7];
        *(float4*)&C[(size_t)row * Nc + col0 + tx * 8] = o0;
        *(float4*)&C[(size_t)row * Nc + col0 + tx * 8 + 4] = o1;
    }
}

// ---------------------------------------------------------------------------
// Flash-attention (round-2 proven version, verbatim).
// Grid: (B*H, N/64). Block: 256 threads (16x16 logical).
// ---------------------------------------------------------------------------
__global__ void attn_kernel(const float* __restrict__ dec)
{
    extern __shared__ float sm[];
    float* Qs = sm;                 // 64*64
    float* Ks = Qs + 64 * 64;       // 64*65 (padded rows)
    float* Vs = Ks + 64 * 65;       // 64*64
    float* Ps = Vs + 64 * 64;       // 64*64

    const int bh = blockIdx.x;
    const int b = bh / NH;
    const int h = bh % NH;
    const int q0 = blockIdx.y * 64;

    const int tid = threadIdx.x;
    const int tx = tid & 15;        // key-col group / out-dim group
    const int ty = tid >> 4;        // query-row group

    // Load Q tile [64 x 64]
    for (int it = 0; it < 4; it++) {
        int t = tid + it * 256;        // 0..1023
        int rr = t >> 4;               // 0..63
        int cc = (t & 15) << 2;        // 0..60
        float4 v = *(const float4*)(dec + (size_t)(b * NN + q0 + rr) * DIM
                                    + h * HD + cc);
        *(float4*)&Qs[rr * 64 + cc] = v;
    }

    float m[4], l[4], o[4][4];
    #pragma unroll
    for (int i = 0; i < 4; i++) {
        m[i] = -1e30f; l[i] = 0.f;
        #pragma unroll
        for (int j = 0; j < 4; j++) o[i][j] = 0.f;
    }

    const float* kbase = g_kv + (size_t)b * NN * 2 * DIM + h * HD;
    const float* vbase = kbase + DIM;

    for (int k0 = 0; k0 < NN; k0 += 64) {
        __syncthreads();

        for (int it = 0; it < 4; it++) {
            int t = tid + it * 256;
            int rr = t >> 4;
            int cc = (t & 15) << 2;
            float4 kv4 = *(const float4*)(kbase + (size_t)(k0 + rr) * (2 * DIM) + cc);
            Ks[rr * 65 + cc + 0] = kv4.x;
            Ks[rr * 65 + cc + 1] = kv4.y;
            Ks[rr * 65 + cc + 2] = kv4.z;
            Ks[rr * 65 + cc + 3] = kv4.w;
            float4 vv4 = *(const float4*)(vbase + (size_t)(k0 + rr) * (2 * DIM) + cc);
            *(float4*)&Vs[rr * 64 + cc] = vv4;
        }
        __syncthreads();

        float s[4][4] = {};
        #pragma unroll 8
        for (int d = 0; d < 64; d++) {
            float a[4], kk[4];
            #pragma unroll
            for (int i = 0; i < 4; i++) a[i] = Qs[(ty * 4 + i) * 64 + d];
            #pragma unroll
            for (int j = 0; j < 4; j++) kk[j] = Ks[(tx * 4 + j) * 65 + d];
            #pragma unroll
            for (int i = 0; i < 4; i++)
                #pragma unroll
                for (int j = 0; j < 4; j++)
                    s[i][j] += a[i] * kk[j];
        }

        #pragma unroll
        for (int i = 0; i < 4; i++) {
            float mt = -1e30f;
            #pragma unroll
            for (int j = 0; j < 4; j++) {
                s[i][j] *= SCALE;
                mt = fmaxf(mt, s[i][j]);
            }
            #pragma unroll
            for (int off = 8; off > 0; off >>= 1)
                mt = fmaxf(mt, __shfl_xor_sync(0xffffffffu, mt, off, 16));

            float mn = fmaxf(m[i], mt);
            float corr = __expf(m[i] - mn);
            m[i] = mn;
            l[i] *= corr;
            #pragma unroll
            for (int j = 0; j < 4; j++) o[i][j] *= corr;

            float p0 = __expf(s[i][0] - mn);
            float p1 = __expf(s[i][1] - mn);
            float p2 = __expf(s[i][2] - mn);
            float p3 = __expf(s[i][3] - mn);
            float rs = p0 + p1 + p2 + p3;
            float4 pv; pv.x = p0; pv.y = p1; pv.z = p2; pv.w = p3;
            #pragma unroll
            for (int off = 8; off > 0; off >>= 1)
                rs += __shfl_xor_sync(0xffffffffu, rs, off, 16);
            l[i] += rs;

            *(float4*)&Ps[(ty * 4 + i) * 64 + tx * 4] = pv;
        }
        __syncthreads();

        #pragma unroll 8
        for (int j = 0; j < 64; j++) {
            float p[4];
            #pragma unroll
            for (int i = 0; i < 4; i++) p[i] = Ps[(ty * 4 + i) * 64 + j];
            float4 v4 = *(float4*)&Vs[j * 64 + tx * 4];
            #pragma unroll
            for (int i = 0; i < 4; i++) {
                o[i][0] += p[i] * v4.x;
                o[i][1] += p[i] * v4.y;
                o[i][2] += p[i] * v4.z;
                o[i][3] += p[i] * v4.w;
            }
        }
    }

    #pragma unroll
    for (int i = 0; i < 4; i++) {
        float inv = 1.f / l[i];
        int row = q0 + ty * 4 + i;
        float4 out;
        out.x = o[i][0] * inv;
        out.y = o[i][1] * inv;
        out.z = o[i][2] * inv;
        out.w = o[i][3] * inv;
        *(float4*)&g_wa[(size_t)(b * NN + row) * DIM + h * HD + tx * 4] = out;
    }
}

// ---------------------------------------------------------------------------
// Launcher
// ---------------------------------------------------------------------------
extern "C" void kernel_launch(void* const* d_in, const int* in_sizes, int n_in,
                              void* d_out, int out_size)
{
    const float* en    = (const float*)d_in[0];
    const float* dec   = (const float*)d_in[1];
    const float* Wkv   = (const float*)d_in[2];
    const float* bkv   = (const float*)d_in[3];
    const float* Wproj = (const float*)d_in[4];
    const float* bproj = (const float*)d_in[5];
    float* out = (float*)d_out;

    float* kv = nullptr;
    float* wa = nullptr;
    cudaGetSymbolAddress((void**)&kv, g_kv);
    cudaGetSymbolAddress((void**)&wa, g_wa);

    const int M = BB * NN;  // 8192

    // 1) kv = en @ Wkv + bkv : [8192 x 1536]
    {
        dim3 grid((2 * DIM) / 128, M / 128);   // 12 x 64
        gemm_bias_kernel<<<grid, 256>>>(en, Wkv, bkv, kv, M, 2 * DIM, DIM);
    }

    // 2) flash attention -> wa  (round-2 proven 64x64 version)
    {
        const int smem = (64 * 64 + 64 * 65 + 64 * 64 + 64 * 64) * (int)sizeof(float);
        (void)cudaFuncSetAttribute(attn_kernel,
                                   cudaFuncAttributeMaxDynamicSharedMemorySize, smem);
        dim3 grid(BB * NH, NN / 64);           // 96 x 16
        attn_kernel<<<grid, 256, smem>>>(dec);
    }

    // 3) out = wa @ Wproj + bproj : [8192 x 768]
    {
        dim3 grid(DIM / 128, M / 128);         // 6 x 64
        gemm_bias_kernel<<<grid, 256>>>(wa, Wproj, bproj, out, M, DIM, DIM);
    }
}

// round 5
// speedup vs baseline: 1.0795x; 1.0577x over previous
#include <cuda_runtime.h>
#include <math.h>
#include <stdint.h>

#define BB 8
#define NN 1024
#define DIM 768
#define NH 12
#define HD 64
#define SCALE 0.125f   // HD^-0.5

// Scratch (allocation-free rule: __device__ globals)
__device__ float g_kv[(size_t)BB * NN * 2 * DIM];   // [B, N, 2*DIM]
__device__ float g_wa[(size_t)BB * NN * DIM];       // [B, N, DIM]

// ---------------------------------------------------------------------------
// TF32 tensor-core GEMM + bias (3xTF32 for fp32-grade accuracy).
// C[M,Nc] = A[M,K] @ W[K,Nc] + bias.  Block 128x128, BK=16, 256 threads.
// 8 warps as 2(M)x4(N); warp tile 64x32; mma.sync m16n8k8 tf32.
// Smem stride 136: fragment-read bank index = (8k + idx) mod 32 -> conflict-free.
// ---------------------------------------------------------------------------
#define SST 136

__device__ __forceinline__ void mma_tf32(float* d, const uint32_t* a, const uint32_t* b)
{
    asm volatile(
        "mma.sync.aligned.m16n8k8.row.col.f32.tf32.tf32.f32 "
        "{%0,%1,%2,%3}, {%4,%5,%6,%7}, {%8,%9}, {%0,%1,%2,%3};\n"
        : "+f"(d[0]), "+f"(d[1]), "+f"(d[2]), "+f"(d[3])
        : "r"(a[0]), "r"(a[1]), "r"(a[2]), "r"(a[3]), "r"(b[0]), "r"(b[1]));
}

__device__ __forceinline__ void split_tf32(float v, uint32_t& hi, uint32_t& lo)
{
    asm("cvt.rna.tf32.f32 %0, %1;" : "=r"(hi) : "f"(v));
    float rem = v - __uint_as_float(hi);
    asm("cvt.rna.tf32.f32 %0, %1;" : "=r"(lo) : "f"(rem));
}

__global__ __launch_bounds__(256, 2)
void gemm_tf32_kernel(const float* __restrict__ A,
                      const float* __restrict__ W,
                      const float* __restrict__ bias,
                      float* __restrict__ C,
                      int M, int Nc, int K)
{
    __shared__ uint32_t Ah[16][SST], Al[16][SST];   // [k][row]
    __shared__ uint32_t Bh[16][SST], Bl[16][SST];   // [k][col]

    const int tid  = threadIdx.x;
    const int lane = tid & 31;
    const int warp = tid >> 5;        // 0..7
    const int wm   = warp >> 2;       // 0..1 -> 64-row slab
    const int wn   = warp & 3;        // 0..3 -> 32-col slab
    const int row0 = blockIdx.y * 128;
    const int col0 = blockIdx.x * 128;

    const int lg = lane >> 2;         // 0..7
    const int lk = lane & 3;          // 0..3

    float acc[4][4][4];
    #pragma unroll
    for (int mt = 0; mt < 4; mt++)
        #pragma unroll
        for (int nt = 0; nt < 4; nt++)
            #pragma unroll
            for (int u = 0; u < 4; u++) acc[mt][nt][u] = 0.f;

    for (int k0 = 0; k0 < K; k0 += 16) {
        // ---- global -> smem with tf32 hi/lo split ----
        float4 av[2], wv[2];
        #pragma unroll
        for (int it = 0; it < 2; it++) {
            int t = tid + it * 256;                 // 0..511
            int arow = t >> 2;                      // 0..127
            int akc  = (t & 3) << 2;                // 0,4,8,12
            av[it] = *(const float4*)(A + (size_t)(row0 + arow) * K + k0 + akc);
            int bkr = t >> 5;                       // 0..15
            int bnc = (t & 31) << 2;                // 0..124
            wv[it] = *(const float4*)(W + (size_t)(k0 + bkr) * Nc + col0 + bnc);
        }
        __syncthreads();   // prev-iter readers done
        #pragma unroll
        for (int it = 0; it < 2; it++) {
            int t = tid + it * 256;
            int arow = t >> 2;
            int akc  = (t & 3) << 2;
            float va[4] = {av[it].x, av[it].y, av[it].z, av[it].w};
            #pragma unroll
            for (int u = 0; u < 4; u++) {
                uint32_t hb, lb;
                split_tf32(va[u], hb, lb);
                Ah[akc + u][arow] = hb;
                Al[akc + u][arow] = lb;
            }
            int bkr = t >> 5;
            int bnc = (t & 31) << 2;
            float vb[4] = {wv[it].x, wv[it].y, wv[it].z, wv[it].w};
            #pragma unroll
            for (int u = 0; u < 4; u++) {
                uint32_t hb, lb;
                split_tf32(vb[u], hb, lb);
                Bh[bkr][bnc + u] = hb;
                Bl[bkr][bnc + u] = lb;
            }
        }
        __syncthreads();

        // ---- two k8 steps ----
        #pragma unroll
        for (int ks = 0; ks < 2; ks++) {
            const int kk = ks * 8 + lk;
            const int rb = wm * 64 + lg;
            const int nb = wn * 32 + lg;

            uint32_t ah[4][4], al[4][4], bf[4][2];
            #pragma unroll
            for (int mt = 0; mt < 4; mt++) {
                ah[mt][0] = Ah[kk    ][rb + mt * 16];
                ah[mt][1] = Ah[kk    ][rb + mt * 16 + 8];
                ah[mt][2] = Ah[kk + 4][rb + mt * 16];
                ah[mt][3] = Ah[kk + 4][rb + mt * 16 + 8];
            }
            #pragma unroll
            for (int nt = 0; nt < 4; nt++) {
                bf[nt][0] = Bh[kk    ][nb + nt * 8];
                bf[nt][1] = Bh[kk + 4][nb + nt * 8];
            }
            // hi * hi
            #pragma unroll
            for (int mt = 0; mt < 4; mt++)
                #pragma unroll
                for (int nt = 0; nt < 4; nt++)
                    mma_tf32(acc[mt][nt], ah[mt], bf[nt]);
            // lo * hi
            #pragma unroll
            for (int mt = 0; mt < 4; mt++) {
                al[mt][0] = Al[kk    ][rb + mt * 16];
                al[mt][1] = Al[kk    ][rb + mt * 16 + 8];
                al[mt][2] = Al[kk + 4][rb + mt * 16];
                al[mt][3] = Al[kk + 4][rb + mt * 16 + 8];
            }
            #pragma unroll
            for (int mt = 0; mt < 4; mt++)
                #pragma unroll
                for (int nt = 0; nt < 4; nt++)
                    mma_tf32(acc[mt][nt], al[mt], bf[nt]);
            // hi * lo
            #pragma unroll
            for (int nt = 0; nt < 4; nt++) {
                bf[nt][0] = Bl[kk    ][nb + nt * 8];
                bf[nt][1] = Bl[kk + 4][nb + nt * 8];
            }
            #pragma unroll
            for (int mt = 0; mt < 4; mt++)
                #pragma unroll
                for (int nt = 0; nt < 4; nt++)
                    mma_tf32(acc[mt][nt], ah[mt], bf[nt]);
        }
    }

    // ---- epilogue: acc + bias -> C (float2 stores) ----
    #pragma unroll
    for (int nt = 0; nt < 4; nt++) {
        int c = col0 + wn * 32 + nt * 8 + 2 * lk;
        float b0 = bias[c];
        float b1 = bias[c + 1];
        #pragma unroll
        for (int mt = 0; mt < 4; mt++) {
            int r = row0 + wm * 64 + mt * 16 + lg;
            float2 o0, o1;
            o0.x = acc[mt][nt][0] + b0;
            o0.y = acc[mt][nt][1] + b1;
            o1.x = acc[mt][nt][2] + b0;
            o1.y = acc[mt][nt][3] + b1;
            *(float2*)&C[(size_t)r * Nc + c] = o0;
            *(float2*)&C[(size_t)(r + 8) * Nc + c] = o1;
        }
    }
}

// ---------------------------------------------------------------------------
// Flash-attention (round-2 proven version, verbatim).
// Grid: (B*H, N/64). Block: 256 threads (16x16 logical).
// ---------------------------------------------------------------------------
__global__ void attn_kernel(const float* __restrict__ dec)
{
    extern __shared__ float sm[];
    float* Qs = sm;                 // 64*64
    float* Ks = Qs + 64 * 64;       // 64*65 (padded rows)
    float* Vs = Ks + 64 * 65;       // 64*64
    float* Ps = Vs + 64 * 64;       // 64*64

    const int bh = blockIdx.x;
    const int b = bh / NH;
    const int h = bh % NH;
    const int q0 = blockIdx.y * 64;

    const int tid = threadIdx.x;
    const int tx = tid & 15;
    const int ty = tid >> 4;

    for (int it = 0; it < 4; it++) {
        int t = tid + it * 256;
        int rr = t >> 4;
        int cc = (t & 15) << 2;
        float4 v = *(const float4*)(dec + (size_t)(b * NN + q0 + rr) * DIM
                                    + h * HD + cc);
        *(float4*)&Qs[rr * 64 + cc] = v;
    }

    float m[4], l[4], o[4][4];
    #pragma unroll
    for (int i = 0; i < 4; i++) {
        m[i] = -1e30f; l[i] = 0.f;
        #pragma unroll
        for (int j = 0; j < 4; j++) o[i][j] = 0.f;
    }

    const float* kbase = g_kv + (size_t)b * NN * 2 * DIM + h * HD;
    const float* vbase = kbase + DIM;

    for (int k0 = 0; k0 < NN; k0 += 64) {
        __syncthreads();

        for (int it = 0; it < 4; it++) {
            int t = tid + it * 256;
            int rr = t >> 4;
            int cc = (t & 15) << 2;
            float4 kv4 = *(const float4*)(kbase + (size_t)(k0 + rr) * (2 * DIM) + cc);
            Ks[rr * 65 + cc + 0] = kv4.x;
            Ks[rr * 65 + cc + 1] = kv4.y;
            Ks[rr * 65 + cc + 2] = kv4.z;
            Ks[rr * 65 + cc + 3] = kv4.w;
            float4 vv4 = *(const float4*)(vbase + (size_t)(k0 + rr) * (2 * DIM) + cc);
            *(float4*)&Vs[rr * 64 + cc] = vv4;
        }
        __syncthreads();

        float s[4][4] = {};
        #pragma unroll 8
        for (int d = 0; d < 64; d++) {
            float a[4], kk[4];
            #pragma unroll
            for (int i = 0; i < 4; i++) a[i] = Qs[(ty * 4 + i) * 64 + d];
            #pragma unroll
            for (int j = 0; j < 4; j++) kk[j] = Ks[(tx * 4 + j) * 65 + d];
            #pragma unroll
            for (int i = 0; i < 4; i++)
                #pragma unroll
                for (int j = 0; j < 4; j++)
                    s[i][j] += a[i] * kk[j];
        }

        #pragma unroll
        for (int i = 0; i < 4; i++) {
            float mt = -1e30f;
            #pragma unroll
            for (int j = 0; j < 4; j++) {
                s[i][j] *= SCALE;
                mt = fmaxf(mt, s[i][j]);
            }
            #pragma unroll
            for (int off = 8; off > 0; off >>= 1)
                mt = fmaxf(mt, __shfl_xor_sync(0xffffffffu, mt, off, 16));

            float mn = fmaxf(m[i], mt);
            float corr = __expf(m[i] - mn);
            m[i] = mn;
            l[i] *= corr;
            #pragma unroll
            for (int j = 0; j < 4; j++) o[i][j] *= corr;

            float p0 = __expf(s[i][0] - mn);
            float p1 = __expf(s[i][1] - mn);
            float p2 = __expf(s[i][2] - mn);
            float p3 = __expf(s[i][3] - mn);
            float rs = p0 + p1 + p2 + p3;
            float4 pv; pv.x = p0; pv.y = p1; pv.z = p2; pv.w = p3;
            #pragma unroll
            for (int off = 8; off > 0; off >>= 1)
                rs += __shfl_xor_sync(0xffffffffu, rs, off, 16);
            l[i] += rs;

            *(float4*)&Ps[(ty * 4 + i) * 64 + tx * 4] = pv;
        }
        __syncthreads();

        #pragma unroll 8
        for (int j = 0; j < 64; j++) {
            float p[4];
            #pragma unroll
            for (int i = 0; i < 4; i++) p[i] = Ps[(ty * 4 + i) * 64 + j];
            float4 v4 = *(float4*)&Vs[j * 64 + tx * 4];
            #pragma unroll
            for (int i = 0; i < 4; i++) {
                o[i][0] += p[i] * v4.x;
                o[i][1] += p[i] * v4.y;
                o[i][2] += p[i] * v4.z;
                o[i][3] += p[i] * v4.w;
            }
        }
    }

    #pragma unroll
    for (int i = 0; i < 4; i++) {
        float inv = 1.f / l[i];
        int row = q0 + ty * 4 + i;
        float4 out;
        out.x = o[i][0] * inv;
        out.y = o[i][1] * inv;
        out.z = o[i][2] * inv;
        out.w = o[i][3] * inv;
        *(float4*)&g_wa[(size_t)(b * NN + row) * DIM + h * HD + tx * 4] = out;
    }
}

// ---------------------------------------------------------------------------
// Launcher
// ---------------------------------------------------------------------------
extern "C" void kernel_launch(void* const* d_in, const int* in_sizes, int n_in,
                              void* d_out, int out_size)
{
    const float* en    = (const float*)d_in[0];
    const float* dec   = (const float*)d_in[1];
    const float* Wkv   = (const float*)d_in[2];
    const float* bkv   = (const float*)d_in[3];
    const float* Wproj = (const float*)d_in[4];
    const float* bproj = (const float*)d_in[5];
    float* out = (float*)d_out;

    float* kv = nullptr;
    float* wa = nullptr;
    cudaGetSymbolAddress((void**)&kv, g_kv);
    cudaGetSymbolAddress((void**)&wa, g_wa);

    const int M = BB * NN;  // 8192

    // 1) kv = en @ Wkv + bkv : [8192 x 1536]
    {
        dim3 grid((2 * DIM) / 128, M / 128);   // 12 x 64
        gemm_tf32_kernel<<<grid, 256>>>(en, Wkv, bkv, kv, M, 2 * DIM, DIM);
    }

    // 2) flash attention -> wa  (round-2 proven 64x64 version)
    {
        const int smem = (64 * 64 + 64 * 65 + 64 * 64 + 64 * 64) * (int)sizeof(float);
        (void)cudaFuncSetAttribute(attn_kernel,
                                   cudaFuncAttributeMaxDynamicSharedMemorySize, smem);
        dim3 grid(BB * NH, NN / 64);           // 96 x 16
        attn_kernel<<<grid, 256, smem>>>(dec);
    }

    // 3) out = wa @ Wproj + bproj : [8192 x 768]
    {
        dim3 grid(DIM / 128, M / 128);         // 6 x 64
        gemm_tf32_kernel<<<grid, 256>>>(wa, Wproj, bproj, out, M, DIM, DIM);
    }
}

// round 6
// speedup vs baseline: 1.5328x; 1.4200x over previous
#include <cuda_runtime.h>
#include <cuda_bf16.h>
#include <math.h>
#include <stdint.h>

#define BB 8
#define NN 1024
#define DIM 768
#define NH 12
#define HD 64
#define SCALE 0.125f   // HD^-0.5

// Scratch (allocation-free rule: __device__ globals)
__device__ float g_kv[(size_t)BB * NN * 2 * DIM];   // [B, N, 2*DIM]
__device__ float g_wa[(size_t)BB * NN * DIM];       // [B, N, DIM]
__device__ float g_kt[(size_t)BB * NH * HD * NN];   // K^T: [B, H, d, token]

// ---------------------------------------------------------------------------
// Helpers
// ---------------------------------------------------------------------------
__device__ __forceinline__ void mma_tf32(float* d, const uint32_t* a, const uint32_t* b)
{
    asm volatile(
        "mma.sync.aligned.m16n8k8.row.col.f32.tf32.tf32.f32 "
        "{%0,%1,%2,%3}, {%4,%5,%6,%7}, {%8,%9}, {%0,%1,%2,%3};\n"
        : "+f"(d[0]), "+f"(d[1]), "+f"(d[2]), "+f"(d[3])
        : "r"(a[0]), "r"(a[1]), "r"(a[2]), "r"(a[3]), "r"(b[0]), "r"(b[1]));
}

__device__ __forceinline__ void mma_bf16(float* d, const uint32_t* a, const uint32_t* b)
{
    asm volatile(
        "mma.sync.aligned.m16n8k16.row.col.f32.bf16.bf16.f32 "
        "{%0,%1,%2,%3}, {%4,%5,%6,%7}, {%8,%9}, {%0,%1,%2,%3};\n"
        : "+f"(d[0]), "+f"(d[1]), "+f"(d[2]), "+f"(d[3])
        : "r"(a[0]), "r"(a[1]), "r"(a[2]), "r"(a[3]), "r"(b[0]), "r"(b[1]));
}

__device__ __forceinline__ void split_tf32(float v, uint32_t& hi, uint32_t& lo)
{
    asm("cvt.rna.tf32.f32 %0, %1;" : "=r"(hi) : "f"(v));
    float rem = v - __uint_as_float(hi);
    asm("cvt.rna.tf32.f32 %0, %1;" : "=r"(lo) : "f"(rem));
}

// bf16 split: h = bf16-rounded head (as float), r = residual
__device__ __forceinline__ void split_bf(float x, float& h, float& r)
{
    h = __bfloat162float(__float2bfloat16(x));
    r = x - h;
}

// pack two floats as bf16x2 word; pk(x,y): x -> first(k even) slot, y -> second.
// (consistent use everywhere makes half-order convention immaterial)
__device__ __forceinline__ uint32_t pk(float x, float y)
{
    uint32_t r;
    asm("cvt.rn.bf16x2.f32 %0, %1, %2;" : "=r"(r) : "f"(y), "f"(x));
    return r;
}

// ---------------------------------------------------------------------------
// TF32 3x tensor-core GEMM + bias (round-5 proven). Optionally also writes the
// K^T scratch (first DIM output columns) as [b][h][d][token].
// ---------------------------------------------------------------------------
#define SST 136

__global__ __launch_bounds__(256, 2)
void gemm_tf32_kernel(const float* __restrict__ A,
                      const float* __restrict__ W,
                      const float* __restrict__ bias,
                      float* __restrict__ C,
                      float* __restrict__ Kt,
                      int M, int Nc, int K)
{
    __shared__ uint32_t Ah[16][SST], Al[16][SST];
    __shared__ uint32_t Bh[16][SST], Bl[16][SST];

    const int tid  = threadIdx.x;
    const int lane = tid & 31;
    const int warp = tid >> 5;
    const int wm   = warp >> 2;
    const int wn   = warp & 3;
    const int row0 = blockIdx.y * 128;
    const int col0 = blockIdx.x * 128;

    const int lg = lane >> 2;
    const int lk = lane & 3;

    float acc[4][4][4];
    #pragma unroll
    for (int mt = 0; mt < 4; mt++)
        #pragma unroll
        for (int nt = 0; nt < 4; nt++)
            #pragma unroll
            for (int u = 0; u < 4; u++) acc[mt][nt][u] = 0.f;

    for (int k0 = 0; k0 < K; k0 += 16) {
        float4 av[2], wv[2];
        #pragma unroll
        for (int it = 0; it < 2; it++) {
            int t = tid + it * 256;
            int arow = t >> 2;
            int akc  = (t & 3) << 2;
            av[it] = *(const float4*)(A + (size_t)(row0 + arow) * K + k0 + akc);
            int bkr = t >> 5;
            int bnc = (t & 31) << 2;
            wv[it] = *(const float4*)(W + (size_t)(k0 + bkr) * Nc + col0 + bnc);
        }
        __syncthreads();
        #pragma unroll
        for (int it = 0; it < 2; it++) {
            int t = tid + it * 256;
            int arow = t >> 2;
            int akc  = (t & 3) << 2;
            float va[4] = {av[it].x, av[it].y, av[it].z, av[it].w};
            #pragma unroll
            for (int u = 0; u < 4; u++) {
                uint32_t hb, lb;
                split_tf32(va[u], hb, lb);
                Ah[akc + u][arow] = hb;
                Al[akc + u][arow] = lb;
            }
            int bkr = t >> 5;
            int bnc = (t & 31) << 2;
            float vb[4] = {wv[it].x, wv[it].y, wv[it].z, wv[it].w};
            #pragma unroll
            for (int u = 0; u < 4; u++) {
                uint32_t hb, lb;
                split_tf32(vb[u], hb, lb);
                Bh[bkr][bnc + u] = hb;
                Bl[bkr][bnc + u] = lb;
            }
        }
        __syncthreads();

        #pragma unroll
        for (int ks = 0; ks < 2; ks++) {
            const int kk = ks * 8 + lk;
            const int rb = wm * 64 + lg;
            const int nb = wn * 32 + lg;

            uint32_t ah[4][4], al[4][4], bf[4][2];
            #pragma unroll
            for (int mt = 0; mt < 4; mt++) {
                ah[mt][0] = Ah[kk    ][rb + mt * 16];
                ah[mt][1] = Ah[kk    ][rb + mt * 16 + 8];
                ah[mt][2] = Ah[kk + 4][rb + mt * 16];
                ah[mt][3] = Ah[kk + 4][rb + mt * 16 + 8];
            }
            #pragma unroll
            for (int nt = 0; nt < 4; nt++) {
                bf[nt][0] = Bh[kk    ][nb + nt * 8];
                bf[nt][1] = Bh[kk + 4][nb + nt * 8];
            }
            #pragma unroll
            for (int mt = 0; mt < 4; mt++)
                #pragma unroll
                for (int nt = 0; nt < 4; nt++)
                    mma_tf32(acc[mt][nt], ah[mt], bf[nt]);
            #pragma unroll
            for (int mt = 0; mt < 4; mt++) {
                al[mt][0] = Al[kk    ][rb + mt * 16];
                al[mt][1] = Al[kk    ][rb + mt * 16 + 8];
                al[mt][2] = Al[kk + 4][rb + mt * 16];
                al[mt][3] = Al[kk + 4][rb + mt * 16 + 8];
            }
            #pragma unroll
            for (int mt = 0; mt < 4; mt++)
                #pragma unroll
                for (int nt = 0; nt < 4; nt++)
                    mma_tf32(acc[mt][nt], al[mt], bf[nt]);
            #pragma unroll
            for (int nt = 0; nt < 4; nt++) {
                bf[nt][0] = Bl[kk    ][nb + nt * 8];
                bf[nt][1] = Bl[kk + 4][nb + nt * 8];
            }
            #pragma unroll
            for (int mt = 0; mt < 4; mt++)
                #pragma unroll
                for (int nt = 0; nt < 4; nt++)
                    mma_tf32(acc[mt][nt], ah[mt], bf[nt]);
        }
    }

    const bool writeKt = (Kt != nullptr) && (col0 < DIM);
    #pragma unroll
    for (int nt = 0; nt < 4; nt++) {
        int c = col0 + wn * 32 + nt * 8 + 2 * lk;
        float b0 = bias[c];
        float b1 = bias[c + 1];
        #pragma unroll
        for (int mt = 0; mt < 4; mt++) {
            int r = row0 + wm * 64 + mt * 16 + lg;
            float2 o0, o1;
            o0.x = acc[mt][nt][0] + b0;
            o0.y = acc[mt][nt][1] + b1;
            o1.x = acc[mt][nt][2] + b0;
            o1.y = acc[mt][nt][3] + b1;
            *(float2*)&C[(size_t)r * Nc + c] = o0;
            *(float2*)&C[(size_t)(r + 8) * Nc + c] = o1;
            if (writeKt) {
                int bb_ = r >> 10;
                int n_  = r & 1023;              // r+8 stays in same batch (r%16 = lg <= 7)
                int d0  = c & 63;                // even, so d0+1 same head
                int h0  = c >> 6;
                size_t base = (((size_t)bb_ * NH + h0) * HD + d0) * NN;
                Kt[base + n_]            = o0.x;
                Kt[base + NN + n_]       = o0.y;
                Kt[base + n_ + 8]        = o1.x;
                Kt[base + NN + n_ + 8]   = o1.y;
            }
        }
    }
}

// ---------------------------------------------------------------------------
// Tensor-core flash attention (bf16 3-term compensated).
// Grid (B*H, N/128), 256 threads = 8 warps; each warp owns 16 query rows.
// Key tile = 64.  All smem planes are bf16x2 words packed along k:
//   Q,P (A operands): [row][k-pair], row stride 36 words
//   K^T,V (B operands): [k-pair][n], row stride 68 words
// ---------------------------------------------------------------------------
#define QST 36
#define KST 68

__global__ __launch_bounds__(256, 2)
void attn_tc_kernel(const float* __restrict__ dec)
{
    extern __shared__ uint32_t smw[];
    uint32_t* Qh = smw;                    // 128*36
    uint32_t* Ql = Qh + 128 * QST;
    uint32_t* Kh = Ql + 128 * QST;         // 32*68
    uint32_t* Kl = Kh + 32 * KST;
    uint32_t* Vh = Kl + 32 * KST;          // 32*68
    uint32_t* Vl = Vh + 32 * KST;
    uint32_t* Ph = Vl + 32 * KST;          // 128*36
    uint32_t* Pl = Ph + 128 * QST;

    const int bh = blockIdx.x;
    const int b  = bh / NH;
    const int h  = bh % NH;
    const int q0 = blockIdx.y * 128;

    const int tid  = threadIdx.x;
    const int lane = tid & 31;
    const int warp = tid >> 5;
    const int g = lane >> 2;       // 0..7
    const int t = lane & 3;        // 0..3
    const int rb = warp * 16;      // this warp's query-row base (in tile)

    // ---- load Q tile [128 q][64 d], split + pack pairs along d ----
    #pragma unroll
    for (int it = 0; it < 8; it++) {
        int idx = tid + it * 256;          // 0..2047
        int row = idx >> 4;                // 0..127
        int dd  = (idx & 15) << 2;         // 0,4,...,60
        float4 qv = *(const float4*)(dec + (size_t)(b * NN + q0 + row) * DIM
                                     + h * HD + dd);
        float hx, lx, hy, ly, hz, lz, hw, lw;
        split_bf(qv.x, hx, lx); split_bf(qv.y, hy, ly);
        split_bf(qv.z, hz, lz); split_bf(qv.w, hw, lw);
        uint2 wh = {pk(hx, hy), pk(hz, hw)};
        uint2 wl = {pk(lx, ly), pk(lz, lw)};
        *(uint2*)&Qh[row * QST + (dd >> 1)] = wh;
        *(uint2*)&Ql[row * QST + (dd >> 1)] = wl;
    }

    float oacc[8][4];
    #pragma unroll
    for (int nt = 0; nt < 8; nt++)
        #pragma unroll
        for (int u = 0; u < 4; u++) oacc[nt][u] = 0.f;
    float m0 = -1e30f, m1 = -1e30f, l0 = 0.f, l1 = 0.f;

    const float* ktb = g_kt + ((size_t)b * NH + h) * HD * NN;        // [d][token]
    const float* vb  = g_kv + (size_t)b * NN * 2 * DIM + DIM + h * HD; // [token][d]

    for (int kt0 = 0; kt0 < NN; kt0 += 64) {
        __syncthreads();   // K/V buffers free (all warps done with prev PV)

        // ---- load K^T tile (32 d-pairs x 64 keys) + V tile (32 key-pairs x 64 d)
        #pragma unroll
        for (int it = 0; it < 2; it++) {
            int idx = tid + it * 256;      // 0..511
            int kp  = idx >> 4;            // 0..31
            int c4  = (idx & 15) << 2;     // 0..60
            // K^T rows 2kp, 2kp+1 (d), cols kt0+c4.. (tokens)
            const float* p0 = ktb + (size_t)(2 * kp) * NN + kt0 + c4;
            float4 x = *(const float4*)p0;
            float4 y = *(const float4*)(p0 + NN);
            float xh[4], xl[4], yh[4], yl[4];
            split_bf(x.x, xh[0], xl[0]); split_bf(x.y, xh[1], xl[1]);
            split_bf(x.z, xh[2], xl[2]); split_bf(x.w, xh[3], xl[3]);
            split_bf(y.x, yh[0], yl[0]); split_bf(y.y, yh[1], yl[1]);
            split_bf(y.z, yh[2], yl[2]); split_bf(y.w, yh[3], yl[3]);
            uint4 wh = {pk(xh[0], yh[0]), pk(xh[1], yh[1]), pk(xh[2], yh[2]), pk(xh[3], yh[3])};
            uint4 wl = {pk(xl[0], yl[0]), pk(xl[1], yl[1]), pk(xl[2], yl[2]), pk(xl[3], yl[3])};
            *(uint4*)&Kh[kp * KST + c4] = wh;
            *(uint4*)&Kl[kp * KST + c4] = wl;
            // V rows kt0+2kp, kt0+2kp+1 (tokens), cols c4.. (d)
            const float* v0 = vb + (size_t)(kt0 + 2 * kp) * (2 * DIM) + c4;
            float4 a = *(const float4*)v0;
            float4 c = *(const float4*)(v0 + 2 * DIM);
            split_bf(a.x, xh[0], xl[0]); split_bf(a.y, xh[1], xl[1]);
            split_bf(a.z, xh[2], xl[2]); split_bf(a.w, xh[3], xl[3]);
            split_bf(c.x, yh[0], yl[0]); split_bf(c.y, yh[1], yl[1]);
            split_bf(c.z, yh[2], yl[2]); split_bf(c.w, yh[3], yl[3]);
            uint4 vh4 = {pk(xh[0], yh[0]), pk(xh[1], yh[1]), pk(xh[2], yh[2]), pk(xh[3], yh[3])};
            uint4 vl4 = {pk(xl[0], yl[0]), pk(xl[1], yl[1]), pk(xl[2], yl[2]), pk(xl[3], yl[3])};
            *(uint4*)&Vh[kp * KST + c4] = vh4;
            *(uint4*)&Vl[kp * KST + c4] = vl4;
        }
        __syncthreads();

        // ---- S = Q @ K^T : warp computes [16 q][64 keys] ----
        float sacc[8][4];
        #pragma unroll
        for (int nt = 0; nt < 8; nt++)
            #pragma unroll
            for (int u = 0; u < 4; u++) sacc[nt][u] = 0.f;

        #pragma unroll
        for (int kc = 0; kc < 4; kc++) {   // d chunks of 16
            uint32_t qah[4], qal[4];
            int abase = (rb + g) * QST + kc * 8 + t;
            qah[0] = Qh[abase];             qah[1] = Qh[abase + 8 * QST];
            qah[2] = Qh[abase + 4];         qah[3] = Qh[abase + 8 * QST + 4];
            qal[0] = Ql[abase];             qal[1] = Ql[abase + 8 * QST];
            qal[2] = Ql[abase + 4];         qal[3] = Ql[abase + 8 * QST + 4];
            #pragma unroll
            for (int nt = 0; nt < 8; nt++) {
                int bbase = (kc * 8 + t) * KST + nt * 8 + g;
                uint32_t kbh[2] = {Kh[bbase], Kh[bbase + 4 * KST]};
                uint32_t kbl[2] = {Kl[bbase], Kl[bbase + 4 * KST]};
                mma_bf16(sacc[nt], qah, kbh);
                mma_bf16(sacc[nt], qah, kbl);
                mma_bf16(sacc[nt], qal, kbh);
            }
        }

        // ---- online softmax (rows rb+g and rb+g+8, stats in-lane) ----
        float mt0 = -1e30f, mt1 = -1e30f;
        #pragma unroll
        for (int nt = 0; nt < 8; nt++) {
            sacc[nt][0] *= SCALE; sacc[nt][1] *= SCALE;
            sacc[nt][2] *= SCALE; sacc[nt][3] *= SCALE;
            mt0 = fmaxf(mt0, fmaxf(sacc[nt][0], sacc[nt][1]));
            mt1 = fmaxf(mt1, fmaxf(sacc[nt][2], sacc[nt][3]));
        }
        mt0 = fmaxf(mt0, __shfl_xor_sync(0xffffffffu, mt0, 1));
        mt0 = fmaxf(mt0, __shfl_xor_sync(0xffffffffu, mt0, 2));
        mt1 = fmaxf(mt1, __shfl_xor_sync(0xffffffffu, mt1, 1));
        mt1 = fmaxf(mt1, __shfl_xor_sync(0xffffffffu, mt1, 2));

        float mn0 = fmaxf(m0, mt0), mn1 = fmaxf(m1, mt1);
        float corr0 = __expf(m0 - mn0), corr1 = __expf(m1 - mn1);
        m0 = mn0; m1 = mn1;

        float rs0 = 0.f, rs1 = 0.f;
        #pragma unroll
        for (int nt = 0; nt < 8; nt++) {
            float p00 = __expf(sacc[nt][0] - mn0);
            float p01 = __expf(sacc[nt][1] - mn0);
            float p10 = __expf(sacc[nt][2] - mn1);
            float p11 = __expf(sacc[nt][3] - mn1);
            rs0 += p00 + p01;
            rs1 += p10 + p11;
            float ha, la, hb2, lb2;
            split_bf(p00, ha, la); split_bf(p01, hb2, lb2);
            Ph[(rb + g) * QST + 4 * nt + t] = pk(ha, hb2);
            Pl[(rb + g) * QST + 4 * nt + t] = pk(la, lb2);
            split_bf(p10, ha, la); split_bf(p11, hb2, lb2);
            Ph[(rb + g + 8) * QST + 4 * nt + t] = pk(ha, hb2);
            Pl[(rb + g + 8) * QST + 4 * nt + t] = pk(la, lb2);
        }
        rs0 += __shfl_xor_sync(0xffffffffu, rs0, 1);
        rs0 += __shfl_xor_sync(0xffffffffu, rs0, 2);
        rs1 += __shfl_xor_sync(0xffffffffu, rs1, 1);
        rs1 += __shfl_xor_sync(0xffffffffu, rs1, 2);
        l0 = l0 * corr0 + rs0;
        l1 = l1 * corr1 + rs1;

        #pragma unroll
        for (int nt = 0; nt < 8; nt++) {
            oacc[nt][0] *= corr0; oacc[nt][1] *= corr0;
            oacc[nt][2] *= corr1; oacc[nt][3] *= corr1;
        }
        __syncwarp();

        // ---- O += P @ V : warp computes [16 q][64 d] ----
        #pragma unroll
        for (int kc = 0; kc < 4; kc++) {   // key chunks of 16
            uint32_t pah[4], pal[4];
            int abase = (rb + g) * QST + kc * 8 + t;
            pah[0] = Ph[abase];             pah[1] = Ph[abase + 8 * QST];
            pah[2] = Ph[abase + 4];         pah[3] = Ph[abase + 8 * QST + 4];
            pal[0] = Pl[abase];             pal[1] = Pl[abase + 8 * QST];
            pal[2] = Pl[abase + 4];         pal[3] = Pl[abase + 8 * QST + 4];
            #pragma unroll
            for (int nt = 0; nt < 8; nt++) {
                int bbase = (kc * 8 + t) * KST + nt * 8 + g;
                uint32_t vbh[2] = {Vh[bbase], Vh[bbase + 4 * KST]};
                uint32_t vbl[2] = {Vl[bbase], Vl[bbase + 4 * KST]};
                mma_bf16(oacc[nt], pah, vbh);
                mma_bf16(oacc[nt], pah, vbl);
                mma_bf16(oacc[nt], pal, vbh);
            }
        }
    }

    // ---- epilogue: normalize, store ----
    float inv0 = 1.f / l0, inv1 = 1.f / l1;
    int row = q0 + rb + g;
    #pragma unroll
    for (int nt = 0; nt < 8; nt++) {
        int d = nt * 8 + 2 * t;
        float2 u0 = {oacc[nt][0] * inv0, oacc[nt][1] * inv0};
        float2 u1 = {oacc[nt][2] * inv1, oacc[nt][3] * inv1};
        *(float2*)&g_wa[(size_t)(b * NN + row) * DIM + h * HD + d] = u0;
        *(float2*)&g_wa[(size_t)(b * NN + row + 8) * DIM + h * HD + d] = u1;
    }
}

// ---------------------------------------------------------------------------
// Launcher
// ---------------------------------------------------------------------------
extern "C" void kernel_launch(void* const* d_in, const int* in_sizes, int n_in,
                              void* d_out, int out_size)
{
    const float* en    = (const float*)d_in[0];
    const float* dec   = (const float*)d_in[1];
    const float* Wkv   = (const float*)d_in[2];
    const float* bkv   = (const float*)d_in[3];
    const float* Wproj = (const float*)d_in[4];
    const float* bproj = (const float*)d_in[5];
    float* out = (float*)d_out;

    float* kv = nullptr;
    float* wa = nullptr;
    float* kt = nullptr;
    cudaGetSymbolAddress((void**)&kv, g_kv);
    cudaGetSymbolAddress((void**)&wa, g_wa);
    cudaGetSymbolAddress((void**)&kt, g_kt);

    const int M = BB * NN;  // 8192

    // 1) kv = en @ Wkv + bkv, plus K^T scratch
    {
        dim3 grid((2 * DIM) / 128, M / 128);   // 12 x 64
        gemm_tf32_kernel<<<grid, 256>>>(en, Wkv, bkv, kv, kt, M, 2 * DIM, DIM);
    }

    // 2) tensor-core flash attention -> wa
    {
        const int smem = (2 * 128 * QST + 2 * 32 * KST + 2 * 32 * KST
                          + 2 * 128 * QST) * (int)sizeof(uint32_t);   // 108544 B
        (void)cudaFuncSetAttribute(attn_tc_kernel,
                                   cudaFuncAttributeMaxDynamicSharedMemorySize, smem);
        dim3 grid(BB * NH, NN / 128);          // 96 x 8
        attn_tc_kernel<<<grid, 256, smem>>>(dec);
    }

    // 3) out = wa @ Wproj + bproj
    {
        dim3 grid(DIM / 128, M / 128);         // 6 x 64
        gemm_tf32_kernel<<<grid, 256>>>(wa, Wproj, bproj, out, nullptr, M, DIM, DIM);
    }
}

// round 7
// speedup vs baseline: 2.3085x; 1.5060x over previous
#include <cuda_runtime.h>
#include <cuda_bf16.h>
#include <math.h>
#include <stdint.h>

#define BB 8
#define NN 1024
#define DIM 768
#define NH 12
#define HD 64
#define SCALE 0.125f   // HD^-0.5

// Scratch (allocation-free rule: __device__ globals)
__device__ float g_kv[(size_t)BB * NN * 2 * DIM];   // [B, N, 2*DIM]
__device__ float g_wa[(size_t)BB * NN * DIM];       // [B, N, DIM]
__device__ float g_kt[(size_t)BB * NH * HD * NN];   // K^T: [B, H, d, token]

// ---------------------------------------------------------------------------
// Helpers
// ---------------------------------------------------------------------------
__device__ __forceinline__ void mma_bf16(float* d, const uint32_t* a, const uint32_t* b)
{
    asm volatile(
        "mma.sync.aligned.m16n8k16.row.col.f32.bf16.bf16.f32 "
        "{%0,%1,%2,%3}, {%4,%5,%6,%7}, {%8,%9}, {%0,%1,%2,%3};\n"
        : "+f"(d[0]), "+f"(d[1]), "+f"(d[2]), "+f"(d[3])
        : "r"(a[0]), "r"(a[1]), "r"(a[2]), "r"(a[3]), "r"(b[0]), "r"(b[1]));
}

// bf16 split: h = bf16-rounded head (as float), r = residual
__device__ __forceinline__ void split_bf(float x, float& h, float& r)
{
    h = __bfloat162float(__float2bfloat16(x));
    r = x - h;
}

// pack two floats as bf16x2 word; pk(x,y): x -> k-even slot, y -> k-odd slot.
__device__ __forceinline__ uint32_t pk(float x, float y)
{
    uint32_t r;
    asm("cvt.rn.bf16x2.f32 %0, %1, %2;" : "=r"(r) : "f"(y), "f"(x));
    return r;
}

// ---------------------------------------------------------------------------
// bf16 3-term compensated tensor-core GEMM + bias.
// C[M,Nc] = A[M,K] @ W[K,Nc] + bias. Block 128x128, BK=32, 256 threads,
// 8 warps as 2(M)x4(N), warp tile 64x32, mma m16n8k16.
// A planes [row][kpair] stride 20 (conflict-free frag reads: 20g+t mod 32 distinct).
// B planes [kpair][col] stride 136 (8t+g mod 32 distinct).
// Optionally writes K^T scratch [b][h][d][token] for the first DIM columns.
// ---------------------------------------------------------------------------
#define AST 20
#define BST 136

__global__ __launch_bounds__(256, 2)
void gemm_bf16_kernel(const float* __restrict__ A,
                      const float* __restrict__ W,
                      const float* __restrict__ bias,
                      float* __restrict__ C,
                      float* __restrict__ Kt,
                      int M, int Nc, int K)
{
    __shared__ uint32_t Ah[128][AST], Al[128][AST];   // 16 kpairs + pad
    __shared__ uint32_t Bh[16][BST],  Bl[16][BST];    // 128 cols + pad

    const int tid  = threadIdx.x;
    const int lane = tid & 31;
    const int warp = tid >> 5;
    const int wm   = warp >> 2;       // 0..1
    const int wn   = warp & 3;        // 0..3
    const int row0 = blockIdx.y * 128;
    const int col0 = blockIdx.x * 128;

    const int lg = lane >> 2;         // 0..7
    const int lk = lane & 3;          // 0..3

    float acc[4][4][4];
    #pragma unroll
    for (int mt = 0; mt < 4; mt++)
        #pragma unroll
        for (int nt = 0; nt < 4; nt++)
            #pragma unroll
            for (int u = 0; u < 4; u++) acc[mt][nt][u] = 0.f;

    // load mappings
    const int a_row = tid >> 3;            // 0..31 base rows per pass (x4)
    const int a_c4  = (tid & 7) << 2;      // 0,4,...,28  -> kpair pair (c4/2, c4/2+1)
    const int b_u0  = tid >> 5;            // 0..7 (kpair), second pass +8
    const int b_c4  = (tid & 31) << 2;     // 0..124

    for (int k0 = 0; k0 < K; k0 += 32) {
        // ---- stage gmem tiles in registers ----
        float4 av[4];
        #pragma unroll
        for (int it = 0; it < 4; it++) {
            int row = a_row + it * 32;     // 0..127
            av[it] = *(const float4*)(A + (size_t)(row0 + row) * K + k0 + a_c4);
        }
        float4 bv0[2], bv1[2];
        #pragma unroll
        for (int p = 0; p < 2; p++) {
            int u = b_u0 + p * 8;          // kpair 0..15
            const float* wp = W + (size_t)(k0 + 2 * u) * Nc + col0 + b_c4;
            bv0[p] = *(const float4*)wp;
            bv1[p] = *(const float4*)(wp + Nc);
        }
        __syncthreads();   // previous-iteration readers done

        // ---- split + store to smem ----
        #pragma unroll
        for (int it = 0; it < 4; it++) {
            int row = a_row + it * 32;
            int kp0 = a_c4 >> 1;           // even
            float hx, lx, hy, ly, hz, lz, hw, lw;
            split_bf(av[it].x, hx, lx); split_bf(av[it].y, hy, ly);
            split_bf(av[it].z, hz, lz); split_bf(av[it].w, hw, lw);
            uint2 wh = {pk(hx, hy), pk(hz, hw)};
            uint2 wl = {pk(lx, ly), pk(lz, lw)};
            *(uint2*)&Ah[row][kp0] = wh;
            *(uint2*)&Al[row][kp0] = wl;
        }
        #pragma unroll
        for (int p = 0; p < 2; p++) {
            int u = b_u0 + p * 8;
            float h0, l0_, h1, l1_, h2, l2_, h3, l3_;
            float g0, m0_, g1, m1_, g2, m2_, g3, m3_;
            split_bf(bv0[p].x, h0, l0_); split_bf(bv0[p].y, h1, l1_);
            split_bf(bv0[p].z, h2, l2_); split_bf(bv0[p].w, h3, l3_);
            split_bf(bv1[p].x, g0, m0_); split_bf(bv1[p].y, g1, m1_);
            split_bf(bv1[p].z, g2, m2_); split_bf(bv1[p].w, g3, m3_);
            uint4 hh = {pk(h0, g0), pk(h1, g1), pk(h2, g2), pk(h3, g3)};
            uint4 ll = {pk(l0_, m0_), pk(l1_, m1_), pk(l2_, m2_), pk(l3_, m3_)};
            *(uint4*)&Bh[u][b_c4] = hh;
            *(uint4*)&Bl[u][b_c4] = ll;
        }
        __syncthreads();

        // ---- 2 x k16 mma steps ----
        #pragma unroll
        for (int ks = 0; ks < 2; ks++) {
            const int kb = ks * 8;
            uint32_t ah[4][4], al[4][4];
            #pragma unroll
            for (int mt = 0; mt < 4; mt++) {
                int r = wm * 64 + mt * 16 + lg;
                ah[mt][0] = Ah[r    ][kb + lk];
                ah[mt][1] = Ah[r + 8][kb + lk];
                ah[mt][2] = Ah[r    ][kb + lk + 4];
                ah[mt][3] = Ah[r + 8][kb + lk + 4];
                al[mt][0] = Al[r    ][kb + lk];
                al[mt][1] = Al[r + 8][kb + lk];
                al[mt][2] = Al[r    ][kb + lk + 4];
                al[mt][3] = Al[r + 8][kb + lk + 4];
            }
            uint32_t bh_[4][2], bl_[4][2];
            #pragma unroll
            for (int nt = 0; nt < 4; nt++) {
                int cc = wn * 32 + nt * 8 + lg;
                bh_[nt][0] = Bh[kb + lk    ][cc];
                bh_[nt][1] = Bh[kb + lk + 4][cc];
                bl_[nt][0] = Bl[kb + lk    ][cc];
                bl_[nt][1] = Bl[kb + lk + 4][cc];
            }
            #pragma unroll
            for (int mt = 0; mt < 4; mt++)
                #pragma unroll
                for (int nt = 0; nt < 4; nt++) {
                    mma_bf16(acc[mt][nt], ah[mt], bh_[nt]);
                    mma_bf16(acc[mt][nt], ah[mt], bl_[nt]);
                    mma_bf16(acc[mt][nt], al[mt], bh_[nt]);
                }
        }
    }

    // ---- epilogue: acc + bias -> C (+ optional K^T scratch) ----
    const bool writeKt = (Kt != nullptr) && (col0 < DIM);
    #pragma unroll
    for (int nt = 0; nt < 4; nt++) {
        int c = col0 + wn * 32 + nt * 8 + 2 * lk;
        float b0 = bias[c];
        float b1 = bias[c + 1];
        #pragma unroll
        for (int mt = 0; mt < 4; mt++) {
            int r = row0 + wm * 64 + mt * 16 + lg;
            float2 o0, o1;
            o0.x = acc[mt][nt][0] + b0;
            o0.y = acc[mt][nt][1] + b1;
            o1.x = acc[mt][nt][2] + b0;
            o1.y = acc[mt][nt][3] + b1;
            *(float2*)&C[(size_t)r * Nc + c] = o0;
            *(float2*)&C[(size_t)(r + 8) * Nc + c] = o1;
            if (writeKt) {
                int bb_ = r >> 10;
                int n_  = r & 1023;
                int d0  = c & 63;
                int h0  = c >> 6;
                size_t base = (((size_t)bb_ * NH + h0) * HD + d0) * NN;
                Kt[base + n_]            = o0.x;
                Kt[base + NN + n_]       = o0.y;
                Kt[base + n_ + 8]        = o1.x;
                Kt[base + NN + n_ + 8]   = o1.y;
            }
        }
    }
}

// ---------------------------------------------------------------------------
// Tensor-core flash attention (bf16 3-term compensated) — round-6 proven.
// ---------------------------------------------------------------------------
#define QST 36
#define KST 68

__global__ __launch_bounds__(256, 2)
void attn_tc_kernel(const float* __restrict__ dec)
{
    extern __shared__ uint32_t smw[];
    uint32_t* Qh = smw;                    // 128*36
    uint32_t* Ql = Qh + 128 * QST;
    uint32_t* Kh = Ql + 128 * QST;         // 32*68
    uint32_t* Kl = Kh + 32 * KST;
    uint32_t* Vh = Kl + 32 * KST;          // 32*68
    uint32_t* Vl = Vh + 32 * KST;
    uint32_t* Ph = Vl + 32 * KST;          // 128*36
    uint32_t* Pl = Ph + 128 * QST;

    const int bh = blockIdx.x;
    const int b  = bh / NH;
    const int h  = bh % NH;
    const int q0 = blockIdx.y * 128;

    const int tid  = threadIdx.x;
    const int lane = tid & 31;
    const int warp = tid >> 5;
    const int g = lane >> 2;
    const int t = lane & 3;
    const int rb = warp * 16;

    #pragma unroll
    for (int it = 0; it < 8; it++) {
        int idx = tid + it * 256;
        int row = idx >> 4;
        int dd  = (idx & 15) << 2;
        float4 qv = *(const float4*)(dec + (size_t)(b * NN + q0 + row) * DIM
                                     + h * HD + dd);
        float hx, lx, hy, ly, hz, lz, hw, lw;
        split_bf(qv.x, hx, lx); split_bf(qv.y, hy, ly);
        split_bf(qv.z, hz, lz); split_bf(qv.w, hw, lw);
        uint2 wh = {pk(hx, hy), pk(hz, hw)};
        uint2 wl = {pk(lx, ly), pk(lz, lw)};
        *(uint2*)&Qh[row * QST + (dd >> 1)] = wh;
        *(uint2*)&Ql[row * QST + (dd >> 1)] = wl;
    }

    float oacc[8][4];
    #pragma unroll
    for (int nt = 0; nt < 8; nt++)
        #pragma unroll
        for (int u = 0; u < 4; u++) oacc[nt][u] = 0.f;
    float m0 = -1e30f, m1 = -1e30f, l0 = 0.f, l1 = 0.f;

    const float* ktb = g_kt + ((size_t)b * NH + h) * HD * NN;
    const float* vb  = g_kv + (size_t)b * NN * 2 * DIM + DIM + h * HD;

    for (int kt0 = 0; kt0 < NN; kt0 += 64) {
        __syncthreads();

        #pragma unroll
        for (int it = 0; it < 2; it++) {
            int idx = tid + it * 256;
            int kp  = idx >> 4;
            int c4  = (idx & 15) << 2;
            const float* p0 = ktb + (size_t)(2 * kp) * NN + kt0 + c4;
            float4 x = *(const float4*)p0;
            float4 y = *(const float4*)(p0 + NN);
            float xh[4], xl[4], yh[4], yl[4];
            split_bf(x.x, xh[0], xl[0]); split_bf(x.y, xh[1], xl[1]);
            split_bf(x.z, xh[2], xl[2]); split_bf(x.w, xh[3], xl[3]);
            split_bf(y.x, yh[0], yl[0]); split_bf(y.y, yh[1], yl[1]);
            split_bf(y.z, yh[2], yl[2]); split_bf(y.w, yh[3], yl[3]);
            uint4 wh = {pk(xh[0], yh[0]), pk(xh[1], yh[1]), pk(xh[2], yh[2]), pk(xh[3], yh[3])};
            uint4 wl = {pk(xl[0], yl[0]), pk(xl[1], yl[1]), pk(xl[2], yl[2]), pk(xl[3], yl[3])};
            *(uint4*)&Kh[kp * KST + c4] = wh;
            *(uint4*)&Kl[kp * KST + c4] = wl;
            const float* v0 = vb + (size_t)(kt0 + 2 * kp) * (2 * DIM) + c4;
            float4 a = *(const float4*)v0;
            float4 c = *(const float4*)(v0 + 2 * DIM);
            split_bf(a.x, xh[0], xl[0]); split_bf(a.y, xh[1], xl[1]);
            split_bf(a.z, xh[2], xl[2]); split_bf(a.w, xh[3], xl[3]);
            split_bf(c.x, yh[0], yl[0]); split_bf(c.y, yh[1], yl[1]);
            split_bf(c.z, yh[2], yl[2]); split_bf(c.w, yh[3], yl[3]);
            uint4 vh4 = {pk(xh[0], yh[0]), pk(xh[1], yh[1]), pk(xh[2], yh[2]), pk(xh[3], yh[3])};
            uint4 vl4 = {pk(xl[0], yl[0]), pk(xl[1], yl[1]), pk(xl[2], yl[2]), pk(xl[3], yl[3])};
            *(uint4*)&Vh[kp * KST + c4] = vh4;
            *(uint4*)&Vl[kp * KST + c4] = vl4;
        }
        __syncthreads();

        float sacc[8][4];
        #pragma unroll
        for (int nt = 0; nt < 8; nt++)
            #pragma unroll
            for (int u = 0; u < 4; u++) sacc[nt][u] = 0.f;

        #pragma unroll
        for (int kc = 0; kc < 4; kc++) {
            uint32_t qah[4], qal[4];
            int abase = (rb + g) * QST + kc * 8 + t;
            qah[0] = Qh[abase];             qah[1] = Qh[abase + 8 * QST];
            qah[2] = Qh[abase + 4];         qah[3] = Qh[abase + 8 * QST + 4];
            qal[0] = Ql[abase];             qal[1] = Ql[abase + 8 * QST];
            qal[2] = Ql[abase + 4];         qal[3] = Ql[abase + 8 * QST + 4];
            #pragma unroll
            for (int nt = 0; nt < 8; nt++) {
                int bbase = (kc * 8 + t) * KST + nt * 8 + g;
                uint32_t kbh[2] = {Kh[bbase], Kh[bbase + 4 * KST]};
                uint32_t kbl[2] = {Kl[bbase], Kl[bbase + 4 * KST]};
                mma_bf16(sacc[nt], qah, kbh);
                mma_bf16(sacc[nt], qah, kbl);
                mma_bf16(sacc[nt], qal, kbh);
            }
        }

        float mt0 = -1e30f, mt1 = -1e30f;
        #pragma unroll
        for (int nt = 0; nt < 8; nt++) {
            sacc[nt][0] *= SCALE; sacc[nt][1] *= SCALE;
            sacc[nt][2] *= SCALE; sacc[nt][3] *= SCALE;
            mt0 = fmaxf(mt0, fmaxf(sacc[nt][0], sacc[nt][1]));
            mt1 = fmaxf(mt1, fmaxf(sacc[nt][2], sacc[nt][3]));
        }
        mt0 = fmaxf(mt0, __shfl_xor_sync(0xffffffffu, mt0, 1));
        mt0 = fmaxf(mt0, __shfl_xor_sync(0xffffffffu, mt0, 2));
        mt1 = fmaxf(mt1, __shfl_xor_sync(0xffffffffu, mt1, 1));
        mt1 = fmaxf(mt1, __shfl_xor_sync(0xffffffffu, mt1, 2));

        float mn0 = fmaxf(m0, mt0), mn1 = fmaxf(m1, mt1);
        float corr0 = __expf(m0 - mn0), corr1 = __expf(m1 - mn1);
        m0 = mn0; m1 = mn1;

        float rs0 = 0.f, rs1 = 0.f;
        #pragma unroll
        for (int nt = 0; nt < 8; nt++) {
            float p00 = __expf(sacc[nt][0] - mn0);
            float p01 = __expf(sacc[nt][1] - mn0);
            float p10 = __expf(sacc[nt][2] - mn1);
            float p11 = __expf(sacc[nt][3] - mn1);
            rs0 += p00 + p01;
            rs1 += p10 + p11;
            float ha, la, hb2, lb2;
            split_bf(p00, ha, la); split_bf(p01, hb2, lb2);
            Ph[(rb + g) * QST + 4 * nt + t] = pk(ha, hb2);
            Pl[(rb + g) * QST + 4 * nt + t] = pk(la, lb2);
            split_bf(p10, ha, la); split_bf(p11, hb2, lb2);
            Ph[(rb + g + 8) * QST + 4 * nt + t] = pk(ha, hb2);
            Pl[(rb + g + 8) * QST + 4 * nt + t] = pk(la, lb2);
        }
        rs0 += __shfl_xor_sync(0xffffffffu, rs0, 1);
        rs0 += __shfl_xor_sync(0xffffffffu, rs0, 2);
        rs1 += __shfl_xor_sync(0xffffffffu, rs1, 1);
        rs1 += __shfl_xor_sync(0xffffffffu, rs1, 2);
        l0 = l0 * corr0 + rs0;
        l1 = l1 * corr1 + rs1;

        #pragma unroll
        for (int nt = 0; nt < 8; nt++) {
            oacc[nt][0] *= corr0; oacc[nt][1] *= corr0;
            oacc[nt][2] *= corr1; oacc[nt][3] *= corr1;
        }
        __syncwarp();

        #pragma unroll
        for (int kc = 0; kc < 4; kc++) {
            uint32_t pah[4], pal[4];
            int abase = (rb + g) * QST + kc * 8 + t;
            pah[0] = Ph[abase];             pah[1] = Ph[abase + 8 * QST];
            pah[2] = Ph[abase + 4];         pah[3] = Ph[abase + 8 * QST + 4];
            pal[0] = Pl[abase];             pal[1] = Pl[abase + 8 * QST];
            pal[2] = Pl[abase + 4];         pal[3] = Pl[abase + 8 * QST + 4];
            #pragma unroll
            for (int nt = 0; nt < 8; nt++) {
                int bbase = (kc * 8 + t) * KST + nt * 8 + g;
                uint32_t vbh[2] = {Vh[bbase], Vh[bbase + 4 * KST]};
                uint32_t vbl[2] = {Vl[bbase], Vl[bbase + 4 * KST]};
                mma_bf16(oacc[nt], pah, vbh);
                mma_bf16(oacc[nt], pah, vbl);
                mma_bf16(oacc[nt], pal, vbh);
            }
        }
    }

    float inv0 = 1.f / l0, inv1 = 1.f / l1;
    int row = q0 + rb + g;
    #pragma unroll
    for (int nt = 0; nt < 8; nt++) {
        int d = nt * 8 + 2 * t;
        float2 u0 = {oacc[nt][0] * inv0, oacc[nt][1] * inv0};
        float2 u1 = {oacc[nt][2] * inv1, oacc[nt][3] * inv1};
        *(float2*)&g_wa[(size_t)(b * NN + row) * DIM + h * HD + d] = u0;
        *(float2*)&g_wa[(size_t)(b * NN + row + 8) * DIM + h * HD + d] = u1;
    }
}

// ---------------------------------------------------------------------------
// Launcher
// ---------------------------------------------------------------------------
extern "C" void kernel_launch(void* const* d_in, const int* in_sizes, int n_in,
                              void* d_out, int out_size)
{
    const float* en    = (const float*)d_in[0];
    const float* dec   = (const float*)d_in[1];
    const float* Wkv   = (const float*)d_in[2];
    const float* bkv   = (const float*)d_in[3];
    const float* Wproj = (const float*)d_in[4];
    const float* bproj = (const float*)d_in[5];
    float* out = (float*)d_out;

    float* kv = nullptr;
    float* wa = nullptr;
    float* kt = nullptr;
    cudaGetSymbolAddress((void**)&kv, g_kv);
    cudaGetSymbolAddress((void**)&wa, g_wa);
    cudaGetSymbolAddress((void**)&kt, g_kt);

    const int M = BB * NN;  // 8192

    // 1) kv = en @ Wkv + bkv, plus K^T scratch
    {
        dim3 grid((2 * DIM) / 128, M / 128);   // 12 x 64
        gemm_bf16_kernel<<<grid, 256>>>(en, Wkv, bkv, kv, kt, M, 2 * DIM, DIM);
    }

    // 2) tensor-core flash attention -> wa
    {
        const int smem = (2 * 128 * QST + 2 * 32 * KST + 2 * 32 * KST
                          + 2 * 128 * QST) * (int)sizeof(uint32_t);   // 108544 B
        (void)cudaFuncSetAttribute(attn_tc_kernel,
                                   cudaFuncAttributeMaxDynamicSharedMemorySize, smem);
        dim3 grid(BB * NH, NN / 128);          // 96 x 8
        attn_tc_kernel<<<grid, 256, smem>>>(dec);
    }

    // 3) out = wa @ Wproj + bproj
    {
        dim3 grid(DIM / 128, M / 128);         // 6 x 64
        gemm_bf16_kernel<<<grid, 256>>>(wa, Wproj, bproj, out, nullptr, M, DIM, DIM);
    }
}